// round 14
// baseline (speedup 1.0000x reference)
#include <cuda_runtime.h>
#include <cstdint>

// Shapes: x (2048,128,32), clusters (32,128,32), out (2048,32)
#define N_TOTAL 2048
#define T_DIM   128
#define F_DIM   32
#define K_DIM   32
#define THREADS 256
#define TCH     16            // t per chunk = one k16 MMA step
#define NCH     8
#define NTILES  16
#define FGROUPS 8

// smem byte offsets (main phase)
#define OFF_XNAT 0
#define XNAT_SZ  32768        // [128 n][16 t] x float4 (4 f's)
#define OFF_CNAT 65536
#define CNAT_SZ  8192         // [32 k][16 t] x float4
#define OFF_AH   81920        // 4 planes x [128][8] u32 (bf16x2, t-pairs)
#define APL      4096
#define OFF_AL   98304
#define OFF_BH   114688       // 4 planes x [32][8] u32
#define BPL      1024
#define OFF_BL   118784
#define SMEM_TOTAL 122880
// epilogue overlays (main buffers dead by then)
#define OFF_X2RED 0           // [1024][4] f32
#define OFF_C2RED 16384       // [256][4] f32
#define OFF_X2S   20480       // [4][128] f32
#define OFF_C2S   22528       // [4][32] f32
#define OFF_EDS   24576       // [4][128][32] f32 (64KB)

__device__ float g_part[FGROUPS * N_TOTAL * K_DIM];   // 2MB partial distances

__device__ __forceinline__ void cp_async16(uint32_t dst, const void* src) {
    asm volatile("cp.async.cg.shared.global [%0], [%1], 16;\n" :: "r"(dst), "l"(src));
}
__device__ __forceinline__ void cp_commit() {
    asm volatile("cp.async.commit_group;\n" ::: "memory");
}
__device__ __forceinline__ void cp_wait1() {
    asm volatile("cp.async.wait_group 1;\n" ::: "memory");
}
__device__ __forceinline__ float fsqrt_approx(float v) {
    float r; asm("sqrt.approx.f32 %0, %1;" : "=f"(r) : "f"(v)); return r;
}
__device__ __forceinline__ float frcp_approx(float v) {
    float r; asm("rcp.approx.f32 %0, %1;" : "=f"(r) : "f"(v)); return r;
}
// pack (a -> low bf16, b -> high bf16); consistent on A and B so layout cancels
__device__ __forceinline__ uint32_t pack_bf16(float a, float b) {
    uint32_t r; asm("cvt.rn.bf16x2.f32 %0, %1, %2;" : "=r"(r) : "f"(b), "f"(a)); return r;
}
__device__ __forceinline__ void mma_bf16(float* d, const uint32_t* a, const uint32_t* b) {
    asm volatile("mma.sync.aligned.m16n8k16.row.col.f32.bf16.bf16.f32 "
        "{%0,%1,%2,%3}, {%4,%5,%6,%7}, {%8,%9}, {%0,%1,%2,%3};"
        : "+f"(d[0]), "+f"(d[1]), "+f"(d[2]), "+f"(d[3])
        : "r"(a[0]), "r"(a[1]), "r"(a[2]), "r"(a[3]), "r"(b[0]), "r"(b[1]));
}
// split one float pair (t even, t odd) into hi/lo bf16x2 words + exact square sum
__device__ __forceinline__ void split_pair(float v0, float v1, uint32_t& hi, uint32_t& lo,
                                           float& sq) {
    hi = pack_bf16(v0, v1);
    float h0 = __uint_as_float(hi << 16);
    float h1 = __uint_as_float(hi & 0xFFFF0000u);
    lo = pack_bf16(v0 - h0, v1 - h1);
    sq = fmaf(v0, v0, fmaf(v1, v1, sq));
}

// ================= Kernel 1: bf16-split HMMA partial distances ================
extern "C" __global__ void __launch_bounds__(THREADS, 1)
ts_mma_kernel(const float* __restrict__ x, const float* __restrict__ clusters) {
    extern __shared__ char smem[];
    const uint32_t sb = (uint32_t)__cvta_generic_to_shared(smem);

    const int tid  = threadIdx.x;
    const int lane = tid & 31;
    const int w    = tid >> 5;
    const int fg   = blockIdx.x & 7;            // f-group (4 f's)
    const int n0   = (blockIdx.x >> 3) * 128;   // n-tile base
    const int f    = w >> 1;                    // warp's f plane (0..3)
    const int mh   = w & 1;                     // m-half (64 rows)
    const int g    = lane >> 2;                 // groupID
    const int t4   = lane & 3;                  // threadID in group

    // ---- cp.async natural-tile addressing ------------------------------------
    // x cells: idx = tid + 256r (r<8): n = (tid>>4)+16r, t = tid&15
    const char* xsrc = (const char*)x
        + ((size_t)(n0 + (tid >> 4)) * T_DIM + (tid & 15)) * (F_DIM * 4) + (size_t)fg * 16;
    const char* csrc = (const char*)clusters
        + ((size_t)(tid >> 4) * T_DIM + (tid & 15)) * (F_DIM * 4) + (size_t)fg * 16;
    const uint32_t xdst = sb + OFF_XNAT + (uint32_t)tid * 16;
    const uint32_t cdst = sb + OFF_CNAT + (uint32_t)tid * 16;

    auto prefetch = [&](int ci) {
        if (ci >= NCH) return;
        const size_t tadv = (size_t)ci * TCH * (F_DIM * 4);       // 2048B per chunk
        const uint32_t xo = (uint32_t)(ci & 1) * XNAT_SZ;
        const uint32_t co = (uint32_t)(ci & 1) * CNAT_SZ;
        #pragma unroll
        for (int r = 0; r < 8; r++)     // 2048 x-cells
            cp_async16(xdst + xo + (uint32_t)(r * 4096), xsrc + tadv + (size_t)r * 262144);
        #pragma unroll
        for (int r = 0; r < 2; r++)     // 512 c-cells
            cp_async16(cdst + co + (uint32_t)(r * 4096), csrc + tadv + (size_t)r * 262144);
    };

    // ---- accumulators --------------------------------------------------------
    float acc[4][4][4];                 // [m-tile][n-tile][frag]
    #pragma unroll
    for (int mt = 0; mt < 4; mt++)
        #pragma unroll
        for (int nt = 0; nt < 4; nt++)
            #pragma unroll
            for (int e = 0; e < 4; e++) acc[mt][nt][e] = 0.f;
    float x2pr[4][4];                   // per r-slot (fixed n), per f
    float c2pr[4];
    #pragma unroll
    for (int r = 0; r < 4; r++)
        #pragma unroll
        for (int ff = 0; ff < 4; ff++) x2pr[r][ff] = 0.f;
    #pragma unroll
    for (int ff = 0; ff < 4; ff++) c2pr[ff] = 0.f;

    prefetch(0); cp_commit();

    for (int ci = 0; ci < NCH; ci++) {
        prefetch(ci + 1); cp_commit();   // uniform group count (empty tail)
        cp_wait1();
        __syncthreads();                  // natural ci visible; planes free (post-MMA sync)

        const float4* xn = (const float4*)(smem + OFF_XNAT + (ci & 1) * XNAT_SZ);
        const float4* cn = (const float4*)(smem + OFF_CNAT + (ci & 1) * CNAT_SZ);

        // ---- transpose + split: x -> A planes (hi/lo), accumulate x^2 --------
        #pragma unroll
        for (int r = 0; r < 4; r++) {
            const int cell = tid + 256 * r;
            const int n  = cell >> 3;
            const int tp = cell & 7;
            float4 v0 = xn[n * 16 + 2 * tp];
            float4 v1 = xn[n * 16 + 2 * tp + 1];
            uint32_t hi, lo;
            uint32_t* AH0 = (uint32_t*)(smem + OFF_AH) + n * 8 + tp;
            uint32_t* AL0 = (uint32_t*)(smem + OFF_AL) + n * 8 + tp;
            split_pair(v0.x, v1.x, hi, lo, x2pr[r][0]); AH0[0*1024] = hi; AL0[0*1024] = lo;
            split_pair(v0.y, v1.y, hi, lo, x2pr[r][1]); AH0[1*1024] = hi; AL0[1*1024] = lo;
            split_pair(v0.z, v1.z, hi, lo, x2pr[r][2]); AH0[2*1024] = hi; AL0[2*1024] = lo;
            split_pair(v0.w, v1.w, hi, lo, x2pr[r][3]); AH0[3*1024] = hi; AL0[3*1024] = lo;
        }
        // ---- transpose + split: c -> B planes --------------------------------
        {
            const int k  = tid >> 3;
            const int tp = tid & 7;
            float4 v0 = cn[k * 16 + 2 * tp];
            float4 v1 = cn[k * 16 + 2 * tp + 1];
            uint32_t hi, lo;
            uint32_t* BH0 = (uint32_t*)(smem + OFF_BH) + k * 8 + tp;
            uint32_t* BL0 = (uint32_t*)(smem + OFF_BL) + k * 8 + tp;
            split_pair(v0.x, v1.x, hi, lo, c2pr[0]); BH0[0*256] = hi; BL0[0*256] = lo;
            split_pair(v0.y, v1.y, hi, lo, c2pr[1]); BH0[1*256] = hi; BL0[1*256] = lo;
            split_pair(v0.z, v1.z, hi, lo, c2pr[2]); BH0[2*256] = hi; BL0[2*256] = lo;
            split_pair(v0.w, v1.w, hi, lo, c2pr[3]); BH0[3*256] = hi; BL0[3*256] = lo;
        }
        __syncthreads();                 // planes written

        // ---- warp MMAs: 4 m-tiles x 4 n-tiles x 3 split terms ----------------
        {
            const uint32_t* AH = (const uint32_t*)(smem + OFF_AH) + f * (APL / 4);
            const uint32_t* AL = (const uint32_t*)(smem + OFF_AL) + f * (APL / 4);
            const uint32_t* BH = (const uint32_t*)(smem + OFF_BH) + f * (BPL / 4);
            const uint32_t* BL = (const uint32_t*)(smem + OFF_BL) + f * (BPL / 4);

            uint32_t bh[4][2], bl[4][2];
            #pragma unroll
            for (int nt = 0; nt < 4; nt++) {
                int row = nt * 8 + g;
                bh[nt][0] = BH[row * 8 + t4];  bh[nt][1] = BH[row * 8 + t4 + 4];
                bl[nt][0] = BL[row * 8 + t4];  bl[nt][1] = BL[row * 8 + t4 + 4];
            }
            #pragma unroll
            for (int mt = 0; mt < 4; mt++) {
                int r0 = mh * 64 + mt * 16 + g;
                uint32_t ah[4], al[4];
                ah[0] = AH[r0 * 8 + t4];       ah[1] = AH[(r0 + 8) * 8 + t4];
                ah[2] = AH[r0 * 8 + t4 + 4];   ah[3] = AH[(r0 + 8) * 8 + t4 + 4];
                al[0] = AL[r0 * 8 + t4];       al[1] = AL[(r0 + 8) * 8 + t4];
                al[2] = AL[r0 * 8 + t4 + 4];   al[3] = AL[(r0 + 8) * 8 + t4 + 4];
                #pragma unroll
                for (int nt = 0; nt < 4; nt++) {
                    mma_bf16(acc[mt][nt], ah, bh[nt]);   // hi*hi
                    mma_bf16(acc[mt][nt], al, bh[nt]);   // lo*hi
                    mma_bf16(acc[mt][nt], ah, bl[nt]);   // hi*lo
                }
            }
        }
        __syncthreads();                 // MMAs done -> planes free for next chunk
    }

    // ---- epilogue: reduce x2/c2, sqrt per f, reduce f, write global ----------
    float* x2red = (float*)(smem + OFF_X2RED);   // [1024][4]
    float* c2red = (float*)(smem + OFF_C2RED);   // [256][4]
    float* x2s   = (float*)(smem + OFF_X2S);     // [4][128]
    float* c2s   = (float*)(smem + OFF_C2S);     // [4][32]
    float* eds   = (float*)(smem + OFF_EDS);     // [4][128][32]

    #pragma unroll
    for (int r = 0; r < 4; r++)
        #pragma unroll
        for (int ff = 0; ff < 4; ff++)
            x2red[(tid + 256 * r) * 4 + ff] = x2pr[r][ff];
    #pragma unroll
    for (int ff = 0; ff < 4; ff++) c2red[tid * 4 + ff] = c2pr[ff];
    __syncthreads();

    if (tid < 128) {
        #pragma unroll
        for (int ff = 0; ff < 4; ff++) {
            float s = 0.f;
            #pragma unroll
            for (int j = 0; j < 8; j++) s += x2red[(tid * 8 + j) * 4 + ff];
            x2s[ff * 128 + tid] = s;
        }
    } else if (tid < 160) {
        int k = tid - 128;
        #pragma unroll
        for (int ff = 0; ff < 4; ff++) {
            float s = 0.f;
            #pragma unroll
            for (int j = 0; j < 8; j++) s += c2red[(k * 8 + j) * 4 + ff];
            c2s[ff * 32 + k] = s;
        }
    }
    __syncthreads();

    // sqrt pass: thread's D fragments -> eds[f][row][k]
    {
        const float* x2f = x2s + f * 128;
        const float* c2f = c2s + f * 32;
        float* ef = eds + f * 4096;
        #pragma unroll
        for (int mt = 0; mt < 4; mt++) {
            int r0 = mh * 64 + mt * 16 + g, r1 = r0 + 8;
            float xa = x2f[r0], xb = x2f[r1];
            #pragma unroll
            for (int nt = 0; nt < 4; nt++) {
                int k0 = nt * 8 + t4 * 2, k1 = k0 + 1;
                float ca = c2f[k0], cb = c2f[k1];
                ef[r0 * 32 + k0] = fsqrt_approx(fmaxf(fmaf(-2.f, acc[mt][nt][0], xa + ca), 0.f));
                ef[r0 * 32 + k1] = fsqrt_approx(fmaxf(fmaf(-2.f, acc[mt][nt][1], xa + cb), 0.f));
                ef[r1 * 32 + k0] = fsqrt_approx(fmaxf(fmaf(-2.f, acc[mt][nt][2], xb + ca), 0.f));
                ef[r1 * 32 + k1] = fsqrt_approx(fmaxf(fmaf(-2.f, acc[mt][nt][3], xb + cb), 0.f));
            }
        }
    }
    __syncthreads();

    #pragma unroll
    for (int i = 0; i < 16; i++) {       // 4096 (n,k) pairs
        int p = tid + 256 * i;
        int n = p >> 5, k = p & 31;
        float tot = eds[0 * 4096 + p] + eds[1 * 4096 + p]
                  + eds[2 * 4096 + p] + eds[3 * 4096 + p];
        g_part[((size_t)fg * N_TOTAL + n0 + n) * K_DIM + k] = tot;
    }
}

// ================= Kernel 2: reduce f-groups + Student-t ======================
extern "C" __global__ void __launch_bounds__(256, 1)
ts_softassign_kernel(float* __restrict__ out) {
    const int w    = threadIdx.x >> 5;
    const int lane = threadIdx.x & 31;           // = k
    const int n    = blockIdx.x * 8 + w;

    float d = 0.f;
    #pragma unroll
    for (int fgi = 0; fgi < FGROUPS; fgi++)
        d += g_part[((size_t)fgi * N_TOTAL + n) * K_DIM + lane];

    float q = frcp_approx(fmaf(d, d, 1.0f));     // alpha = 1
    float s = q;
    #pragma unroll
    for (int off = 16; off > 0; off >>= 1)
        s += __shfl_xor_sync(0xffffffffu, s, off);
    out[(size_t)n * K_DIM + lane] = q * frcp_approx(s);
}

extern "C" void kernel_launch(void* const* d_in, const int* in_sizes, int n_in,
                              void* d_out, int out_size) {
    const float* x        = (const float*)d_in[0];   // (2048, 128, 32)
    const float* clusters = (const float*)d_in[1];   // (32, 128, 32)
    float* out            = (float*)d_out;           // (2048, 32)
    (void)in_sizes; (void)n_in; (void)out_size;

    cudaFuncSetAttribute(ts_mma_kernel,
                         cudaFuncAttributeMaxDynamicSharedMemorySize, SMEM_TOTAL);
    ts_mma_kernel<<<NTILES * FGROUPS, THREADS, SMEM_TOTAL>>>(x, clusters);
    ts_softassign_kernel<<<N_TOTAL / 8, 256>>>(out);
}